// round 1
// baseline (speedup 1.0000x reference)
#include <cuda_runtime.h>

#define NN 32768
#define KK 4000
#define DD 128
#define CC 1000

#define BM 128
#define BN 128
#define TM 8
#define TN 8
#define TSTRIDE 132   // padded row length (floats) for transposed tiles
#define NTHREADS 256

__device__ float g_x2[NN];
__device__ float g_p2[KK];
__device__ int   g_idx[NN];

// ---------------------------------------------------------------------------
// Row squared-norms: one warp per row, 8 rows per 256-thread block.
// ---------------------------------------------------------------------------
__global__ void row_norm_kernel(const float* __restrict__ A, float* __restrict__ out, int rows) {
    int row  = blockIdx.x * 8 + (threadIdx.x >> 5);
    int lane = threadIdx.x & 31;
    if (row >= rows) return;
    const float* a = A + (size_t)row * DD;
    float s = 0.f;
#pragma unroll
    for (int i = 0; i < DD / 32; i++) {
        float v = a[lane + 32 * i];
        s = fmaf(v, v, s);
    }
#pragma unroll
    for (int o = 16; o > 0; o >>= 1) s += __shfl_down_sync(0xffffffffu, s, o);
    if (lane == 0) out[row] = s;
}

// ---------------------------------------------------------------------------
// Fused score-GEMM + running argmin.
// score(n,k) = (x2[n] - 2*dot(x_n, p_k)) + p2[k]   (same association as ref)
// Tiles stored TRANSPOSED in smem: [d][row] so the inner-loop fragment loads
// are contiguous (proxy frag) / broadcast (x frag) -> conflict-free.
// ---------------------------------------------------------------------------
extern __shared__ float smem_dyn[];

__global__ __launch_bounds__(NTHREADS, 1)
void argmin_kernel(const float* __restrict__ x, const float* __restrict__ p) {
    float* xsT = smem_dyn;                  // [DD][TSTRIDE]
    float* psT = xsT + DD * TSTRIDE;        // [DD][TSTRIDE]
    float* x2s = psT + DD * TSTRIDE;        // [BM]
    float* p2s = x2s + BM;                  // [BN]

    int tid = threadIdx.x;
    int tx  = tid & 15;     // proxy-group 0..15
    int ty  = tid >> 4;     // row-group 0..15
    int rowBase = blockIdx.x * BM;

    // Load + transpose the x tile (done once per block).
    for (int i = tid; i < BM * DD / 4; i += NTHREADS) {
        int r = i >> 5;             // i / (DD/4)
        int c = (i & 31) << 2;      // float4 column
        float4 v = *(const float4*)(x + (size_t)(rowBase + r) * DD + c);
        xsT[(c + 0) * TSTRIDE + r] = v.x;
        xsT[(c + 1) * TSTRIDE + r] = v.y;
        xsT[(c + 2) * TSTRIDE + r] = v.z;
        xsT[(c + 3) * TSTRIDE + r] = v.w;
    }
    if (tid < BM) x2s[tid] = g_x2[rowBase + tid];

    float bestv[TM];
    int   besti[TM];
#pragma unroll
    for (int i = 0; i < TM; i++) { bestv[i] = 3.0e38f; besti[i] = 0; }

    for (int kt = 0; kt < KK; kt += BN) {
        __syncthreads();   // protect psT from previous iteration's readers
        // Load + transpose the proxy tile (zero-pad past K).
        for (int i = tid; i < BN * DD / 4; i += NTHREADS) {
            int r = i >> 5;
            int c = (i & 31) << 2;
            int kg = kt + r;
            float4 v = make_float4(0.f, 0.f, 0.f, 0.f);
            if (kg < KK) v = *(const float4*)(p + (size_t)kg * DD + c);
            psT[(c + 0) * TSTRIDE + r] = v.x;
            psT[(c + 1) * TSTRIDE + r] = v.y;
            psT[(c + 2) * TSTRIDE + r] = v.z;
            psT[(c + 3) * TSTRIDE + r] = v.w;
        }
        if (tid < BN) p2s[tid] = (kt + tid < KK) ? g_p2[kt + tid] : 3.0e38f;
        __syncthreads();

        float acc[TM][TN];
#pragma unroll
        for (int i = 0; i < TM; i++)
#pragma unroll
            for (int j = 0; j < TN; j++) acc[i][j] = 0.f;

        const float* xb = xsT + ty * TM;
        const float* pb = psT + tx * TN;
#pragma unroll 2
        for (int d = 0; d < DD; d++) {
            float4 xa = *(const float4*)(xb + d * TSTRIDE);
            float4 xc = *(const float4*)(xb + d * TSTRIDE + 4);
            float4 pa = *(const float4*)(pb + d * TSTRIDE);
            float4 pc = *(const float4*)(pb + d * TSTRIDE + 4);
            float xv[TM] = {xa.x, xa.y, xa.z, xa.w, xc.x, xc.y, xc.z, xc.w};
            float pv[TN] = {pa.x, pa.y, pa.z, pa.w, pc.x, pc.y, pc.z, pc.w};
#pragma unroll
            for (int i = 0; i < TM; i++)
#pragma unroll
                for (int j = 0; j < TN; j++)
                    acc[i][j] = fmaf(xv[i], pv[j], acc[i][j]);
        }

        // Running argmin update. k scanned ascending within this thread; strict
        // '<' keeps the first (lowest-index) minimum, matching jnp.argmin.
#pragma unroll
        for (int j = 0; j < TN; j++) {
            int   kg = kt + tx * TN + j;
            float pp = p2s[tx * TN + j];
#pragma unroll
            for (int i = 0; i < TM; i++) {
                float s = (x2s[ty * TM + i] - 2.0f * acc[i][j]) + pp;
                if (s < bestv[i]) { bestv[i] = s; besti[i] = kg; }
            }
        }
    }

    // Cross-thread reduction: 16 threads (tx) hold candidates for each row.
    __syncthreads();
    float* redv = psT;                        // [16][BM] floats (reuse psT)
    int*   redi = (int*)(psT + 16 * BM);      // [16][BM] ints
#pragma unroll
    for (int i = 0; i < TM; i++) {
        int row = ty * TM + i;
        redv[tx * BM + row] = bestv[i];
        redi[tx * BM + row] = besti[i];
    }
    __syncthreads();
    if (tid < BM) {
        float bv = 3.4e38f;
        int   bi = 0x7fffffff;
        for (int t = 0; t < 16; t++) {
            float v  = redv[t * BM + tid];
            int   ix = redi[t * BM + tid];
            if (v < bv || (v == bv && ix < bi)) { bv = v; bi = ix; }
        }
        g_idx[rowBase + tid] = bi;
    }
}

// ---------------------------------------------------------------------------
// Output assembly: out = [ x (N*D) | proxies[idx] (N*D) | labels[idx] (N*C) ]
// One block per row; all float4. labels (16MB) lives in L2 after first wave.
// ---------------------------------------------------------------------------
__global__ void gather_kernel(const float* __restrict__ x, const float* __restrict__ p,
                              const float* __restrict__ lab, float* __restrict__ out) {
    int row = blockIdx.x;
    int tid = threadIdx.x;
    int idx = g_idx[row];

    const float4* xr = (const float4*)(x + (size_t)row * DD);
    float4*       o0 = (float4*)(out + (size_t)row * DD);
    const float4* pr = (const float4*)(p + (size_t)idx * DD);
    float4*       o1 = (float4*)(out + (size_t)NN * DD + (size_t)row * DD);
    const float4* lr = (const float4*)(lab + (size_t)idx * CC);
    float4*       o2 = (float4*)(out + 2 * (size_t)NN * DD + (size_t)row * CC);

    if (tid < 32)       o0[tid]      = xr[tid];
    else if (tid < 64)  o1[tid - 32] = pr[tid - 32];
    for (int i = tid; i < CC / 4; i += blockDim.x) o2[i] = lr[i];
}

// ---------------------------------------------------------------------------
extern "C" void kernel_launch(void* const* d_in, const int* in_sizes, int n_in,
                              void* d_out, int out_size) {
    const float* x   = (const float*)d_in[0];
    const float* p   = (const float*)d_in[1];
    const float* lab = (const float*)d_in[2];
    float* out = (float*)d_out;

    float *px2 = nullptr, *pp2 = nullptr;
    cudaGetSymbolAddress((void**)&px2, g_x2);
    cudaGetSymbolAddress((void**)&pp2, g_p2);

    size_t smem = (size_t)(2 * DD * TSTRIDE + BM + BN) * sizeof(float);
    cudaFuncSetAttribute(argmin_kernel, cudaFuncAttributeMaxDynamicSharedMemorySize, (int)smem);

    row_norm_kernel<<<NN / 8, 256>>>(x, px2, NN);
    row_norm_kernel<<<(KK + 7) / 8, 256>>>(p, pp2, KK);
    argmin_kernel<<<NN / BM, NTHREADS, smem>>>(x, p);
    gather_kernel<<<NN, 256>>>(x, p, lab, out);
}

// round 3
// speedup vs baseline: 1.1886x; 1.1886x over previous
#include <cuda_runtime.h>
#include <cstdint>

#define NN 32768
#define KK 4000
#define DD 128
#define CC 1000

#define BM 128
#define BN 128
#define TM 4
#define TN 8
#define TSTRIDE 132   // padded row length (floats) for transposed tiles
#define NTHREADS 512

__device__ float g_x2[NN];
__device__ float g_p2[KK];
__device__ int   g_idx[NN];

// ---------------------------------------------------------------------------
// Packed f32x2 helpers (sm_103a FFMA2 path)
// ---------------------------------------------------------------------------
__device__ __forceinline__ uint64_t ffma2(uint64_t a, uint64_t b, uint64_t c) {
    uint64_t d;
    asm("fma.rn.f32x2 %0, %1, %2, %3;" : "=l"(d) : "l"(a), "l"(b), "l"(c));
    return d;
}
__device__ __forceinline__ uint64_t pack2(float lo, float hi) {
    uint64_t d;
    asm("mov.b64 %0, {%1, %2};" : "=l"(d) : "f"(lo), "f"(hi));
    return d;
}
__device__ __forceinline__ float2 unpack2(uint64_t v) {
    float2 r;
    asm("mov.b64 {%0, %1}, %2;" : "=f"(r.x), "=f"(r.y) : "l"(v));
    return r;
}

// ---------------------------------------------------------------------------
// Row squared-norms: one warp per row, 8 rows per 256-thread block.
// ---------------------------------------------------------------------------
__global__ void row_norm_kernel(const float* __restrict__ A, float* __restrict__ out, int rows) {
    int row  = blockIdx.x * 8 + (threadIdx.x >> 5);
    int lane = threadIdx.x & 31;
    if (row >= rows) return;
    const float* a = A + (size_t)row * DD;
    float s = 0.f;
#pragma unroll
    for (int i = 0; i < DD / 32; i++) {
        float v = a[lane + 32 * i];
        s = fmaf(v, v, s);
    }
#pragma unroll
    for (int o = 16; o > 0; o >>= 1) s += __shfl_down_sync(0xffffffffu, s, o);
    if (lane == 0) out[row] = s;
}

// ---------------------------------------------------------------------------
// Fused score-GEMM + running argmin, packed f32x2 FMAs.
// score(n,k) = (x2[n] - 2*dot(x_n, p_k)) + p2[k]
// Tiles transposed in smem [d][row]: proxy fragment LDS.128 yields two packed
// f32x2 operands directly; x fragment is splat-packed via mov.b64.
// ---------------------------------------------------------------------------
extern __shared__ float smem_dyn[];

__global__ __launch_bounds__(NTHREADS, 1)
void argmin_kernel(const float* __restrict__ x, const float* __restrict__ p) {
    float* xsT = smem_dyn;                  // [DD][TSTRIDE]
    float* psT = xsT + DD * TSTRIDE;        // [DD][TSTRIDE]
    float* x2s = psT + DD * TSTRIDE;        // [BM]
    float* p2s = x2s + BM;                  // [BN]

    int tid = threadIdx.x;
    int tx  = tid & 15;     // proxy-group 0..15 (TN=8 each)
    int ty  = tid >> 4;     // row-group 0..31   (TM=4 each)
    int rowBase = blockIdx.x * BM;

    // Load + transpose the x tile (once per block).
    for (int i = tid; i < BM * DD / 4; i += NTHREADS) {
        int r = i >> 5;             // i / (DD/4)
        int c = (i & 31) << 2;      // float4 column
        float4 v = *(const float4*)(x + (size_t)(rowBase + r) * DD + c);
        xsT[(c + 0) * TSTRIDE + r] = v.x;
        xsT[(c + 1) * TSTRIDE + r] = v.y;
        xsT[(c + 2) * TSTRIDE + r] = v.z;
        xsT[(c + 3) * TSTRIDE + r] = v.w;
    }
    if (tid < BM) x2s[tid] = g_x2[rowBase + tid];

    float bestv[TM];
    int   besti[TM];
#pragma unroll
    for (int i = 0; i < TM; i++) { bestv[i] = 3.0e38f; besti[i] = 0; }

    for (int kt = 0; kt < KK; kt += BN) {
        __syncthreads();   // protect psT from previous iteration's readers
        for (int i = tid; i < BN * DD / 4; i += NTHREADS) {
            int r = i >> 5;
            int c = (i & 31) << 2;
            int kg = kt + r;
            float4 v = make_float4(0.f, 0.f, 0.f, 0.f);
            if (kg < KK) v = *(const float4*)(p + (size_t)kg * DD + c);
            psT[(c + 0) * TSTRIDE + r] = v.x;
            psT[(c + 1) * TSTRIDE + r] = v.y;
            psT[(c + 2) * TSTRIDE + r] = v.z;
            psT[(c + 3) * TSTRIDE + r] = v.w;
        }
        if (tid < BN) p2s[tid] = (kt + tid < KK) ? g_p2[kt + tid] : 3.0e38f;
        __syncthreads();

        uint64_t acc[TM][TN / 2];
#pragma unroll
        for (int i = 0; i < TM; i++)
#pragma unroll
            for (int j = 0; j < TN / 2; j++) acc[i][j] = 0ull;

        const float* xb = xsT + ty * TM;
        const float* pb = psT + tx * TN;
#pragma unroll 4
        for (int d = 0; d < DD; d++) {
            float4     xa = *(const float4*)(xb + d * TSTRIDE);
            ulonglong2 pA = *(const ulonglong2*)(pb + d * TSTRIDE);
            ulonglong2 pB = *(const ulonglong2*)(pb + d * TSTRIDE + 4);
            uint64_t xs[TM] = { pack2(xa.x, xa.x), pack2(xa.y, xa.y),
                                pack2(xa.z, xa.z), pack2(xa.w, xa.w) };
            uint64_t pv[TN / 2] = { pA.x, pA.y, pB.x, pB.y };
#pragma unroll
            for (int i = 0; i < TM; i++)
#pragma unroll
                for (int j = 0; j < TN / 2; j++)
                    acc[i][j] = ffma2(xs[i], pv[j], acc[i][j]);
        }

        // Running argmin. k ascending inside each thread; strict '<' keeps the
        // first (lowest-index) minimum, matching jnp.argmin.
#pragma unroll
        for (int j = 0; j < TN / 2; j++) {
            int kg = kt + tx * TN + 2 * j;
#pragma unroll
            for (int i = 0; i < TM; i++) {
                float2 dp = unpack2(acc[i][j]);
                float  xr = x2s[ty * TM + i];
                float s0 = (xr - 2.0f * dp.x) + p2s[tx * TN + 2 * j];
                float s1 = (xr - 2.0f * dp.y) + p2s[tx * TN + 2 * j + 1];
                if (s0 < bestv[i]) { bestv[i] = s0; besti[i] = kg; }
                if (s1 < bestv[i]) { bestv[i] = s1; besti[i] = kg + 1; }
            }
        }
    }

    // Cross-thread reduction: 16 threads (tx) hold candidates per row.
    __syncthreads();
    float* redv = psT;                        // [16][BM] floats (reuse psT)
    int*   redi = (int*)(psT + 16 * BM);      // [16][BM] ints
#pragma unroll
    for (int i = 0; i < TM; i++) {
        int row = ty * TM + i;
        redv[tx * BM + row] = bestv[i];
        redi[tx * BM + row] = besti[i];
    }
    __syncthreads();
    if (tid < BM) {
        float bv = 3.4e38f;
        int   bi = 0x7fffffff;
        for (int t = 0; t < 16; t++) {
            float v  = redv[t * BM + tid];
            int   ix = redi[t * BM + tid];
            if (v < bv || (v == bv && ix < bi)) { bv = v; bi = ix; }
        }
        g_idx[rowBase + tid] = bi;
    }
}

// ---------------------------------------------------------------------------
// Output assembly: out = [ x (N*D) | proxies[idx] (N*D) | labels[idx] (N*C) ]
// Streaming stores (__stcs) keep output writes from evicting the 16MB labels
// table out of L2 (label reads should stay L2-resident).
// ---------------------------------------------------------------------------
__global__ void gather_kernel(const float* __restrict__ x, const float* __restrict__ p,
                              const float* __restrict__ lab, float* __restrict__ out) {
    int row = blockIdx.x;
    int tid = threadIdx.x;
    int idx = g_idx[row];

    const float4* xr = (const float4*)(x + (size_t)row * DD);
    float4*       o0 = (float4*)(out + (size_t)row * DD);
    const float4* pr = (const float4*)(p + (size_t)idx * DD);
    float4*       o1 = (float4*)(out + (size_t)NN * DD + (size_t)row * DD);
    const float4* lr = (const float4*)(lab + (size_t)idx * CC);
    float4*       o2 = (float4*)(out + 2 * (size_t)NN * DD + (size_t)row * CC);

    if (tid < 32)       __stcs(o0 + tid,      xr[tid]);
    else if (tid < 64)  __stcs(o1 + tid - 32, pr[tid - 32]);
    for (int i = tid; i < CC / 4; i += blockDim.x) __stcs(o2 + i, lr[i]);
}

// ---------------------------------------------------------------------------
extern "C" void kernel_launch(void* const* d_in, const int* in_sizes, int n_in,
                              void* d_out, int out_size) {
    const float* x   = (const float*)d_in[0];
    const float* p   = (const float*)d_in[1];
    const float* lab = (const float*)d_in[2];
    float* out = (float*)d_out;

    float *px2 = nullptr, *pp2 = nullptr;
    cudaGetSymbolAddress((void**)&px2, g_x2);
    cudaGetSymbolAddress((void**)&pp2, g_p2);

    size_t smem = (size_t)(2 * DD * TSTRIDE + BM + BN) * sizeof(float);
    cudaFuncSetAttribute(argmin_kernel, cudaFuncAttributeMaxDynamicSharedMemorySize, (int)smem);

    row_norm_kernel<<<NN / 8, 256>>>(x, px2, NN);
    row_norm_kernel<<<(KK + 7) / 8, 256>>>(p, pp2, KK);
    argmin_kernel<<<NN / BM, NTHREADS, smem>>>(x, p);
    gather_kernel<<<NN, 256>>>(x, p, lab, out);
}